// round 7
// baseline (speedup 1.0000x reference)
#include <cuda_runtime.h>
#include <cuda_bf16.h>
#include <math.h>
#include <stdint.h>

#define B     128
#define H     1024
#define Z     256
#define SRC   64
#define KMAX  48
#define BH    (B*H)
#define X0LD  2560          // [z(256) | k(1) | attn(1024) | pad(255) | h0(1024)]
#define X1LD  2048          // [h0n | h1]
#define G4    4096
#define KS_GATE 4
#define KS_GEN  8
#define KS_OUT  16
#define NC0   80            // X0LD/32
#define NC1   64            // X1LD/32
#define NCG   32            // 1024/32
#define NCO   64            // 2048/32

// out layout: z[B,K,Z] | mu | sigma | h_f[2,B,H] | c_f[2,B,H]
#define OUT_MU 1572864
#define OUT_SG 3145728
#define OUT_H  4718592
#define OUT_C  4980736

#define TILEB 4096          // bf16 elements per 128x32 W block

typedef __nv_bfloat16 bf;

// ---------------- device scratch ----------------
__device__ __align__(16) float g_x0[B*X0LD];
__device__ __align__(16) float g_x1[B*X1LD];
__device__ __align__(16) float g_xa[B*X1LD];        // [weighted | q]
__device__ __align__(16) float g_c[2*BH];
__device__ __align__(16) float g_part[16*B*G4];     // split-K partials
__device__ __align__(16) bf g_w0h[G4*X0LD], g_w0l[G4*X0LD];
__device__ __align__(16) bf g_w1h[G4*X1LD], g_w1l[G4*X1LD];
__device__ __align__(16) bf g_wgh[1536*H], g_wgl[1536*H];
__device__ __align__(16) bf g_woh[H*2048], g_wol[H*2048];

// monotonic grid barrier state (never reset; consistent across graph replays)
__device__ unsigned long long g_arrive;
__device__ unsigned long long g_release;

__device__ __forceinline__ float sigm(float x){ return 1.f/(1.f+expf(-x)); }

__device__ __forceinline__ void grid_bar(){
    __syncthreads();
    if (threadIdx.x == 0) {
        __threadfence();
        unsigned long long tk = atomicAdd(&g_arrive, 1ULL);
        unsigned long long gen = tk >> 7;                 // 128 CTAs per generation
        if ((tk & 127ULL) == 127ULL) {
            atomicAdd(&g_release, 1ULL);
        } else {
            while (*(volatile unsigned long long*)&g_release <= gen) __nanosleep(64);
        }
        __threadfence();
    }
    __syncthreads();
}

__device__ __forceinline__ void mma16816(float* c, const uint32_t* a, const uint32_t* b){
    asm volatile("mma.sync.aligned.m16n8k16.row.col.f32.bf16.bf16.f32 "
        "{%0,%1,%2,%3}, {%4,%5,%6,%7}, {%8,%9}, {%0,%1,%2,%3};"
        : "+f"(c[0]),"+f"(c[1]),"+f"(c[2]),"+f"(c[3])
        : "r"(a[0]),"r"(a[1]),"r"(a[2]),"r"(a[3]), "r"(b[0]),"r"(b[1]));
}

// ---------------- GEMM phase (bf16x3 via mma.sync), one code copy ----------------
__device__ __noinline__ void gemm_phase(char* smraw, const float* A, int lda,
    const bf* __restrict__ Whi, const bf* __restrict__ Wlo,
    int NCg, int KPS, int ntile, int z)
{
    bf (*sAh)[40] = (bf(*)[40])(smraw);
    bf (*sAl)[40] = (bf(*)[40])(smraw + 10240);
    bf (*sWh)[40] = (bf(*)[40])(smraw + 20480);
    bf (*sWl)[40] = (bf(*)[40])(smraw + 30720);

    const int t = threadIdx.x;
    const int w = t >> 5, lane = t & 31;
    const int g = lane >> 2, tig = lane & 3;
    const int n0 = ntile << 7;
    const int mrow = (w & 1) << 6;
    const int ncol = (w >> 1) << 5;
    const int lrow = t >> 1;
    const int lofs = (t & 1) << 4;

    const float* aptr = A + (size_t)lrow * lda + lofs + (size_t)(z * KPS) * 32;
    const bf* whp = Whi + ((size_t)(ntile * NCg + z * KPS) * 128 + lrow) * 32 + lofs;
    const bf* wlp = Wlo + ((size_t)(ntile * NCg + z * KPS) * 128 + lrow) * 32 + lofs;

    float acc[4][4][4];
#pragma unroll
    for (int i=0;i<4;i++)
#pragma unroll
        for (int j=0;j<4;j++)
#pragma unroll
            for (int q2=0;q2<4;q2++) acc[i][j][q2]=0.f;

    float4 fa0, fa1, fa2, fa3;
    uint4 wh0, wh1, wl0, wl1;
    fa0 = *(const float4*)(aptr);     fa1 = *(const float4*)(aptr+4);
    fa2 = *(const float4*)(aptr+8);   fa3 = *(const float4*)(aptr+12);
    wh0 = *(const uint4*)(whp);       wh1 = *(const uint4*)(whp+8);
    wl0 = *(const uint4*)(wlp);       wl1 = *(const uint4*)(wlp+8);

    for (int ci = 0; ci < KPS; ci++) {
        __syncthreads();
        {
            float fv[16] = {fa0.x,fa0.y,fa0.z,fa0.w, fa1.x,fa1.y,fa1.z,fa1.w,
                            fa2.x,fa2.y,fa2.z,fa2.w, fa3.x,fa3.y,fa3.z,fa3.w};
            bf hv[16], lv[16];
#pragma unroll
            for (int j=0;j<16;j++){
                hv[j] = __float2bfloat16(fv[j]);
                lv[j] = __float2bfloat16(fv[j] - __bfloat162float(hv[j]));
            }
            *(uint4*)&sAh[lrow][lofs]   = *(uint4*)&hv[0];
            *(uint4*)&sAh[lrow][lofs+8] = *(uint4*)&hv[8];
            *(uint4*)&sAl[lrow][lofs]   = *(uint4*)&lv[0];
            *(uint4*)&sAl[lrow][lofs+8] = *(uint4*)&lv[8];
            *(uint4*)&sWh[lrow][lofs]   = wh0;
            *(uint4*)&sWh[lrow][lofs+8] = wh1;
            *(uint4*)&sWl[lrow][lofs]   = wl0;
            *(uint4*)&sWl[lrow][lofs+8] = wl1;
        }
        __syncthreads();
        if (ci + 1 < KPS) {
            const float* ap = aptr + (ci+1)*32;
            const bf* wp1 = whp + (size_t)(ci+1)*TILEB;
            const bf* wp2 = wlp + (size_t)(ci+1)*TILEB;
            fa0 = *(const float4*)(ap);    fa1 = *(const float4*)(ap+4);
            fa2 = *(const float4*)(ap+8);  fa3 = *(const float4*)(ap+12);
            wh0 = *(const uint4*)(wp1);    wh1 = *(const uint4*)(wp1+8);
            wl0 = *(const uint4*)(wp2);    wl1 = *(const uint4*)(wp2+8);
        }
#pragma unroll
        for (int k16 = 0; k16 < 32; k16 += 16) {
            uint32_t Ah[4][4], Al[4][4], Bh[4][2], Bl[4][2];
            const int kk = k16 + tig*2;
#pragma unroll
            for (int mt=0; mt<4; mt++){
                int r = mrow + mt*16 + g;
                Ah[mt][0] = *(const uint32_t*)&sAh[r][kk];
                Ah[mt][1] = *(const uint32_t*)&sAh[r+8][kk];
                Ah[mt][2] = *(const uint32_t*)&sAh[r][kk+8];
                Ah[mt][3] = *(const uint32_t*)&sAh[r+8][kk+8];
                Al[mt][0] = *(const uint32_t*)&sAl[r][kk];
                Al[mt][1] = *(const uint32_t*)&sAl[r+8][kk];
                Al[mt][2] = *(const uint32_t*)&sAl[r][kk+8];
                Al[mt][3] = *(const uint32_t*)&sAl[r+8][kk+8];
            }
#pragma unroll
            for (int nt=0; nt<4; nt++){
                int r = ncol + nt*8 + g;
                Bh[nt][0] = *(const uint32_t*)&sWh[r][kk];
                Bh[nt][1] = *(const uint32_t*)&sWh[r][kk+8];
                Bl[nt][0] = *(const uint32_t*)&sWl[r][kk];
                Bl[nt][1] = *(const uint32_t*)&sWl[r][kk+8];
            }
#pragma unroll
            for (int mt=0;mt<4;mt++)
#pragma unroll
                for (int nt=0;nt<4;nt++){
                    mma16816(acc[mt][nt], Ah[mt], Bh[nt]);
                    mma16816(acc[mt][nt], Ah[mt], Bl[nt]);
                    mma16816(acc[mt][nt], Al[mt], Bh[nt]);
                }
        }
    }

#pragma unroll
    for (int mt=0; mt<4; mt++){
        int r0 = mrow + mt*16 + g;
#pragma unroll
        for (int nt=0; nt<4; nt++){
            int col = n0 + ncol + nt*8 + tig*2;
            float* p0 = g_part + ((size_t)(z*128 + r0))*4096 + col;
            float* p1 = g_part + ((size_t)(z*128 + r0 + 8))*4096 + col;
            *(float2*)p0 = make_float2(acc[mt][nt][0], acc[mt][nt][1]);
            *(float2*)p1 = make_float2(acc[mt][nt][2], acc[mt][nt][3]);
        }
    }
}

// ---------------- element-wise phases ----------------
__device__ __forceinline__ void lstm_phase(float* hst, int ldh, float* cst,
    float* hout, int ldo, const float* bi, const float* bh,
    const int* kin, int step, int cta)
{
    for (int i = cta*256 + threadIdx.x; i < BH; i += 32768) {
        int b = i >> 10, hh = i & 1023;
        float gv[4];
#pragma unroll
        for (int gi=0; gi<4; gi++) {
            int col = (gi<<10) + hh;
            float s = bi[col] + bh[col];
#pragma unroll
            for (int zz=0; zz<KS_GATE; zz++)
                s += g_part[((size_t)(zz*128+b))*4096 + col];
            gv[gi] = s;
        }
        float* hp = hst + (size_t)b*ldh + hh;
        float ho = *hp, co = cst[i];
        float cn = sigm(gv[1])*co + sigm(gv[0])*tanhf(gv[2]);
        float hn = sigm(gv[3])*tanhf(cn);
        hout[(size_t)b*ldo + hh] = hn;
        bool frozen = step >= kin[b];
        *hp    = frozen ? ho : hn;
        cst[i] = frozen ? co : cn;
    }
}

__device__ __forceinline__ void attn_phase(char* smraw, const float* ctx, float* out,
    const float* eps, const float* mub, const float* sgb,
    const int* kin, int step, int b)
{
    float* sq  = (float*)smraw;            // 1024 floats
    float* sal = (float*)(smraw + 4096);   // 64 floats
    int t = threadIdx.x;

    if (step >= 0) {                       // fused zstep
        int zi = t;
        float m = mub[zi], s = sgb[zi];
#pragma unroll
        for (int zz=0; zz<KS_GEN; zz++) {
            const float* p = g_part + ((size_t)(zz*128+b))*4096;
            m += p[zi];
            s += p[256+zi];
        }
        float zval = m + expf(s) * eps[((size_t)step*B + b)*Z + zi];
        g_x0[(size_t)b*X0LD + zi] = zval;
        bool valid = step < kin[b];
        size_t o = ((size_t)b*KMAX + step)*Z + zi;
        out[o]          = valid ? zval : 0.f;
        out[OUT_MU + o] = valid ? m : 0.f;
        out[OUT_SG + o] = valid ? s : 0.f;
    }

    for (int i=t; i<H; i+=256) {           // qw reduce (cols 512..1535)
        float s = 0.f;
#pragma unroll
        for (int zz=0; zz<KS_GEN; zz++)
            s += g_part[((size_t)(zz*128+b))*4096 + 512 + i];
        sq[i] = s;
    }
    __syncthreads();
    int warp = t>>5, lane = t&31;
#pragma unroll
    for (int s8=0; s8<8; s8++) {
        int s = warp*8 + s8;
        const float* cr = ctx + ((size_t)b*SRC + s)*H;
        float a = 0.f;
        for (int k2=lane; k2<H; k2+=32) a += cr[k2]*sq[k2];
#pragma unroll
        for (int o=16;o>0;o>>=1) a += __shfl_xor_sync(0xffffffffu, a, o);
        if (lane==0) sal[s] = a;
    }
    __syncthreads();
    if (warp==0) {
        float v0 = sal[lane], v1 = sal[lane+32];
        float mx = fmaxf(v0,v1);
#pragma unroll
        for (int o=16;o>0;o>>=1) mx = fmaxf(mx, __shfl_xor_sync(0xffffffffu,mx,o));
        float e0=expf(v0-mx), e1=expf(v1-mx);
        float sm=e0+e1;
#pragma unroll
        for (int o=16;o>0;o>>=1) sm += __shfl_xor_sync(0xffffffffu,sm,o);
        float inv=1.f/sm;
        sal[lane]=e0*inv; sal[lane+32]=e1*inv;
    }
    __syncthreads();
    for (int hh=t; hh<H; hh+=256) {
        float a=0.f;
#pragma unroll 8
        for (int s=0;s<SRC;s++) a += sal[s]*ctx[((size_t)b*SRC+s)*H + hh];
        g_xa[(size_t)b*X1LD + hh] = a;
    }
}

__device__ __forceinline__ void attnout_phase(int cta)
{
    for (int i = cta*256 + threadIdx.x; i < BH; i += 32768) {
        int b = i>>10, hh = i&1023;
        float s = 0.f;
#pragma unroll
        for (int zz=0; zz<KS_OUT; zz++)
            s += g_part[((size_t)(zz*128+b))*4096 + hh];
        g_x0[(size_t)b*X0LD + 257 + hh] = tanhf(s);
    }
}

// ---------------- persistent kernel ----------------
__global__ __launch_bounds__(256) void persist(
    const float* __restrict__ h0, const float* __restrict__ c0,
    const float* __restrict__ ctx, const float* __restrict__ z0,
    const int* __restrict__ kin, const float* __restrict__ eps,
    const float* __restrict__ b_ih0, const float* __restrict__ b_hh0,
    const float* __restrict__ b_ih1, const float* __restrict__ b_hh1,
    const float* __restrict__ mu_b, const float* __restrict__ sg_b,
    float* __restrict__ out)
{
    __shared__ __align__(16) char sm[40960];
    const int cta = blockIdx.x, t = threadIdx.x;

    // ---- init ----
    for (int i = cta*256 + t; i < B*X0LD; i += 32768) {
        int b = i / X0LD, c = i - b*X0LD;
        float v = 0.f;
        if (c < 256)        v = z0[(b<<8) + c];
        else if (c == 256)  v = (float)kin[b];
        else if (c >= 1536) v = h0[(b<<10) + (c-1536)];
        g_x0[i] = v;
    }
    for (int i = cta*256 + t; i < B*X1LD; i += 32768) {
        int b = i >> 11, c = i & 2047;
        g_x1[i] = (c < 1024) ? 0.f : h0[BH + (b<<10) + (c-1024)];
        g_xa[i] = (c < 1024) ? 0.f : c0[BH + (b<<10) + (c-1024)];
        g_c[i]  = c0[i];
    }
    grid_bar();

    // ---- attn0: q = c0[-1] ----
    if (cta < 96) gemm_phase(sm, c0 + BH, H, g_wgh, g_wgl, NCG, NCG/KS_GEN, cta>>3, cta&7);
    grid_bar();
    attn_phase(sm, ctx, out, eps, mu_b, sg_b, kin, -1, cta);
    grid_bar();
    gemm_phase(sm, g_xa, X1LD, g_woh, g_wol, NCO, NCO/KS_OUT, cta>>4, cta&15);
    grid_bar();
    attnout_phase(cta);
    grid_bar();

    for (int step = 0; step < KMAX; step++) {
        gemm_phase(sm, g_x0, X0LD, g_w0h, g_w0l, NC0, NC0/KS_GATE, cta>>2, cta&3);
        grid_bar();
        lstm_phase(g_x0 + 1536, X0LD, g_c, g_x1, X1LD, b_ih0, b_hh0, kin, step, cta);
        grid_bar();
        gemm_phase(sm, g_x1, X1LD, g_w1h, g_w1l, NC1, NC1/KS_GATE, cta>>2, cta&3);
        grid_bar();
        lstm_phase(g_x1 + 1024, X1LD, g_c + BH, g_xa + 1024, X1LD, b_ih1, b_hh1, kin, step, cta);
        grid_bar();
        if (cta < 96) gemm_phase(sm, g_xa + 1024, X1LD, g_wgh, g_wgl, NCG, NCG/KS_GEN, cta>>3, cta&7);
        grid_bar();
        attn_phase(sm, ctx, out, eps, mu_b, sg_b, kin, step, cta);
        grid_bar();
        gemm_phase(sm, g_xa, X1LD, g_woh, g_wol, NCO, NCO/KS_OUT, cta>>4, cta&15);
        grid_bar();
        attnout_phase(cta);
        grid_bar();
    }

    // ---- final copy ----
    for (int i = cta*256 + t; i < BH; i += 32768) {
        int b = i>>10, hh = i&1023;
        out[OUT_H + i]      = g_x0[(size_t)b*X0LD + 1536 + hh];
        out[OUT_H + BH + i] = g_x1[(size_t)b*X1LD + 1024 + hh];
        out[OUT_C + i]      = g_c[i];
        out[OUT_C + BH + i] = g_c[BH + i];
    }
}

// ---------------- weight prep: fp32 -> bf16 hi/lo blocked ----------------
__device__ __forceinline__ void put_tile(bf* hi, bf* lo, int NCg, int n, int k, float v){
    int ntile = n >> 7, nin = n & 127, chunk = k >> 5, kin = k & 31;
    size_t d = ((size_t)(ntile * NCg + chunk) * 128 + nin) * 32 + kin;
    bf h = __float2bfloat16(v);
    hi[d] = h;
    lo[d] = __float2bfloat16(v - __bfloat162float(h));
}
__global__ void prep0(const float* __restrict__ Wih, const float* __restrict__ Whh){
    int i = blockIdx.x*256 + threadIdx.x;
    int n = i / X0LD, k = i - n*X0LD;
    float v;
    if (k < 1281)      v = Wih[(size_t)n*1281 + k];
    else if (k < 1536) v = 0.f;
    else               v = Whh[(size_t)n*1024 + (k-1536)];
    put_tile(g_w0h, g_w0l, NC0, n, k, v);
}
__global__ void prep1(const float* __restrict__ Wih, const float* __restrict__ Whh){
    int i = blockIdx.x*256 + threadIdx.x;
    int n = i >> 11, k = i & 2047;
    float v = (k < 1024) ? Wih[(size_t)n*1024 + k] : Whh[(size_t)n*1024 + (k-1024)];
    put_tile(g_w1h, g_w1l, NC1, n, k, v);
}
__global__ void prepg(const float* __restrict__ muW, const float* __restrict__ sgW,
                      const float* __restrict__ aWin){
    int i = blockIdx.x*256 + threadIdx.x;
    int n = i >> 10, k = i & 1023;
    float v;
    if (n < 256)      v = muW[(size_t)n*1024 + k];
    else if (n < 512) v = sgW[(size_t)(n-256)*1024 + k];
    else              v = aWin[(size_t)(n-512)*1024 + k];
    put_tile(g_wgh, g_wgl, NCG, n, k, v);
}
__global__ void prepo(const float* __restrict__ aWout){
    int i = blockIdx.x*256 + threadIdx.x;
    int n = i >> 11, k = i & 2047;
    put_tile(g_woh, g_wol, NCO, n, k, aWout[(size_t)n*2048 + k]);
}

// ---------------- orchestration ----------------
extern "C" void kernel_launch(void* const* d_in, const int* in_sizes, int n_in,
                              void* d_out, int out_size) {
    const float* h0    = (const float*)d_in[0];
    const float* c0    = (const float*)d_in[1];
    const float* ctx   = (const float*)d_in[2];
    const float* z0    = (const float*)d_in[3];
    const int*   kin   = (const int*)  d_in[4];
    const float* eps   = (const float*)d_in[5];
    const float* W_ih0 = (const float*)d_in[6];
    const float* W_hh0 = (const float*)d_in[7];
    const float* b_ih0 = (const float*)d_in[8];
    const float* b_hh0 = (const float*)d_in[9];
    const float* W_ih1 = (const float*)d_in[10];
    const float* W_hh1 = (const float*)d_in[11];
    const float* b_ih1 = (const float*)d_in[12];
    const float* b_hh1 = (const float*)d_in[13];
    const float* aWin  = (const float*)d_in[14];
    const float* aWout = (const float*)d_in[15];
    const float* mu_W  = (const float*)d_in[16];
    const float* mu_b  = (const float*)d_in[17];
    const float* sg_W  = (const float*)d_in[18];
    const float* sg_b  = (const float*)d_in[19];
    float* out = (float*)d_out;

    prep0<<<(G4*X0LD)/256, 256>>>(W_ih0, W_hh0);
    prep1<<<(G4*X1LD)/256, 256>>>(W_ih1, W_hh1);
    prepg<<<(1536*H)/256, 256>>>(mu_W, sg_W, aWin);
    prepo<<<(H*2048)/256, 256>>>(aWout);

    persist<<<128, 256>>>(h0, c0, ctx, z0, kin, eps,
                          b_ih0, b_hh0, b_ih1, b_hh1, mu_b, sg_b, out);

    (void)in_sizes; (void)n_in; (void)out_size;
}